// round 6
// baseline (speedup 1.0000x reference)
#include <cuda_runtime.h>

#define IN_CH   64
#define OUT_CH  64
#define GROUPS  8
#define FPG     8
#define H       256
#define WID     256
#define BATCH   8
#define TY      32
#define SM_W    260   // 258 padded cols + 2 pad -> multiple of 4 for aligned LDS.128

__global__ __launch_bounds__(256, 6) void fused_conv_kernel(const float* __restrict__ x,
                                                            const float* __restrict__ rep,
                                                            const float* __restrict__ W,
                                                            float* __restrict__ out) {
    __shared__ float sm[(TY + 2) * SM_W];   // 34*260*4 = 35360 B
    __shared__ float wsm[FPG * 9];          // 72 dynamic weights for this (b, g)

    const int tileY = blockIdx.x;       // 0..7
    const int g     = blockIdx.y;       // 0..7
    const int b     = blockIdx.z;       // 0..7
    const int tid   = threadIdx.x;

    const float* xg = x + ((size_t)(b * IN_CH + g * FPG)) * (H * WID);

    // ---- weights: leaky_relu(rep[b] . W[row]) for rows g*72 .. g*72+71 ----
    if (tid < FPG * 9) {
        const float4* wr = (const float4*)(W + (size_t)(g * FPG * 9 + tid) * 32);
        const float4* rv = (const float4*)(rep + b * 32);
        float acc = 0.f;
        #pragma unroll
        for (int i = 0; i < 8; ++i) {
            float4 a = wr[i], r = rv[i];
            acc += a.x * r.x + a.y * r.y + a.z * r.z + a.w * r.w;
        }
        wsm[tid] = acc > 0.f ? acc : 0.1f * acc;
    }

    // ---- interior: sum 8 channels into shared, vectorized streaming LDG.128 ----
    // items: 34 padded rows x 64 float4 groups = 2176
    #pragma unroll
    for (int i = 0; i < 9; ++i) {
        int item = tid + i * 256;
        if (item < (TY + 2) * 64) {
            int r  = item >> 6;
            int j4 = item & 63;
            int y = tileY * TY + r - 1;
            y = (y < 0) ? 1 : (y > H - 1 ? H - 2 : y);   // reflect pad=1
            const float4* p = (const float4*)(xg + (size_t)y * WID + 4 * j4);
            float sx = 0.f, sy = 0.f, sz = 0.f, sw = 0.f;
            #pragma unroll
            for (int c = 0; c < FPG; ++c) {
                float4 v = __ldcs(p + c * (H * WID / 4));
                sx += v.x; sy += v.y; sz += v.z; sw += v.w;
            }
            float* d = sm + r * SM_W + 4 * j4 + 1;  // padded col = x+1
            d[0] = sx; d[1] = sy; d[2] = sz; d[3] = sw;
        }
    }
    // ---- halo columns: padded col 0 <- src x=1 ; padded col 257 <- src x=254 ----
    if (tid < 2 * (TY + 2)) {
        int r = tid >> 1, side = tid & 1;
        int y = tileY * TY + r - 1;
        y = (y < 0) ? 1 : (y > H - 1 ? H - 2 : y);
        int xs = side ? (WID - 2) : 1;
        float v = 0.f;
        #pragma unroll
        for (int c = 0; c < FPG; ++c) v += xg[(size_t)c * (H * WID) + (size_t)y * WID + xs];
        sm[r * SM_W + (side ? 257 : 0)] = v;
    }
    __syncthreads();

    // ---- compute: each thread does 1x4 output strips, 8 out channels ----
    const int q  = tid & 63;   // x-quad: outputs x = 4q .. 4q+3
    const int r0 = tid >> 6;   // 0..3
    float* ob = out + ((size_t)(b * OUT_CH + g * FPG)) * (H * WID) + 4 * q;

    #pragma unroll 4
    for (int rr0 = 0; rr0 < TY; rr0 += 4) {
        const int rr = rr0 + r0;
        // window: padded rows rr..rr+2, padded cols 4q..4q+5 (two aligned LDS.128 per row)
        float win[3][6];
        #pragma unroll
        for (int dy = 0; dy < 3; ++dy) {
            const float4* sp = (const float4*)(sm + (rr + dy) * SM_W + 4 * q);
            float4 a = sp[0], bb = sp[1];
            win[dy][0] = a.x;  win[dy][1] = a.y;  win[dy][2] = a.z;  win[dy][3] = a.w;
            win[dy][4] = bb.x; win[dy][5] = bb.y;
        }
        const int y = tileY * TY + rr;
        #pragma unroll
        for (int o = 0; o < 8; ++o) {
            float wo[9];
            #pragma unroll
            for (int j = 0; j < 9; ++j) wo[j] = wsm[o * 9 + j];
            float ax = 0.f, ay = 0.f, az = 0.f, aw = 0.f;
            #pragma unroll
            for (int dy = 0; dy < 3; ++dy) {
                #pragma unroll
                for (int dx = 0; dx < 3; ++dx) {
                    const float wv = wo[dy * 3 + dx];
                    ax += wv * win[dy][dx + 0];
                    ay += wv * win[dy][dx + 1];
                    az += wv * win[dy][dx + 2];
                    aw += wv * win[dy][dx + 3];
                }
            }
            __stcs((float4*)(ob + (size_t)o * (H * WID) + (size_t)y * WID),
                   make_float4(ax, ay, az, aw));
        }
    }
}

extern "C" void kernel_launch(void* const* d_in, const int* in_sizes, int n_in,
                              void* d_out, int out_size) {
    const float* x   = (const float*)d_in[0];
    const float* rep = (const float*)d_in[1];
    const float* W   = (const float*)d_in[2];
    float* out = (float*)d_out;

    dim3 grid(H / TY, GROUPS, BATCH);
    fused_conv_kernel<<<grid, 256>>>(x, rep, W, out);
}

// round 9
// speedup vs baseline: 1.2275x; 1.2275x over previous
#include <cuda_runtime.h>
#include <cstdint>

#define IN_CH   64
#define OUT_CH  64
#define GROUPS  8
#define FPG     8
#define H       256
#define WID     256
#define BATCH   8
#define TY      32
#define SM_W    260   // 258 padded cols + 2 pad -> multiple of 4 for aligned LDS.128

__device__ __forceinline__ uint64_t pk(float lo, float hi) {
    uint64_t r;
    asm("mov.b64 %0, {%1, %2};" : "=l"(r) : "f"(lo), "f"(hi));
    return r;
}
__device__ __forceinline__ void fma2(uint64_t& d, uint64_t a, uint64_t b) {
    asm("fma.rn.f32x2 %0, %1, %2, %3;" : "=l"(d) : "l"(a), "l"(b), "l"(d));
}
__device__ __forceinline__ void unpk(float& lo, float& hi, uint64_t v) {
    asm("mov.b64 {%0, %1}, %2;" : "=f"(lo), "=f"(hi) : "l"(v));
}

__global__ __launch_bounds__(256) void fused_conv_kernel(const float* __restrict__ x,
                                                         const float* __restrict__ rep,
                                                         const float* __restrict__ W,
                                                         float* __restrict__ out) {
    __shared__ float sm[(TY + 2) * SM_W];   // 34*260*4 = 35360 B
    __shared__ uint64_t wsm2[FPG * 9];      // 72 dynamic weights, packed (w,w)

    const int tileY = blockIdx.x;       // 0..7
    const int g     = blockIdx.y;       // 0..7
    const int b     = blockIdx.z;       // 0..7
    const int tid   = threadIdx.x;

    const float* xg = x + ((size_t)(b * IN_CH + g * FPG)) * (H * WID);

    // ---- weights: leaky_relu(rep[b] . W[row]) for rows g*72 .. g*72+71 ----
    if (tid < FPG * 9) {
        const float4* wr = (const float4*)(W + (size_t)(g * FPG * 9 + tid) * 32);
        const float4* rv = (const float4*)(rep + b * 32);
        float acc = 0.f;
        #pragma unroll
        for (int i = 0; i < 8; ++i) {
            float4 a = wr[i], r = rv[i];
            acc += a.x * r.x + a.y * r.y + a.z * r.z + a.w * r.w;
        }
        float lr = acc > 0.f ? acc : 0.1f * acc;
        uint32_t u = __float_as_uint(lr);
        wsm2[tid] = ((uint64_t)u << 32) | u;    // (w, w) packed
    }

    // ---- interior: sum 8 channels into shared, vectorized LDG.128 ----
    // items: 34 padded rows x 64 float4 groups = 2176
    #pragma unroll
    for (int i = 0; i < 9; ++i) {
        int item = tid + i * 256;
        if (item < (TY + 2) * 64) {
            int r  = item >> 6;
            int j4 = item & 63;
            int y = tileY * TY + r - 1;
            y = (y < 0) ? 1 : (y > H - 1 ? H - 2 : y);   // reflect pad=1
            const float4* p = (const float4*)(xg + (size_t)y * WID + 4 * j4);
            float sx = 0.f, sy = 0.f, sz = 0.f, sw = 0.f;
            #pragma unroll
            for (int c = 0; c < FPG; ++c) {
                float4 v = p[c * (H * WID / 4)];
                sx += v.x; sy += v.y; sz += v.z; sw += v.w;
            }
            float* d = sm + r * SM_W + 4 * j4 + 1;  // padded col = x+1
            d[0] = sx; d[1] = sy; d[2] = sz; d[3] = sw;
        }
    }
    // ---- halo columns: padded col 0 <- src x=1 ; padded col 257 <- src x=254 ----
    if (tid < 2 * (TY + 2)) {
        int r = tid >> 1, side = tid & 1;
        int y = tileY * TY + r - 1;
        y = (y < 0) ? 1 : (y > H - 1 ? H - 2 : y);
        int xs = side ? (WID - 2) : 1;
        float v = 0.f;
        #pragma unroll
        for (int c = 0; c < FPG; ++c) v += xg[(size_t)c * (H * WID) + (size_t)y * WID + xs];
        sm[r * SM_W + (side ? 257 : 0)] = v;
    }
    __syncthreads();

    // ---- compute: 1x4 strips, 8 out channels, packed f32x2 FMA ----
    const int q  = tid & 63;   // x-quad: outputs x = 4q .. 4q+3
    const int r0 = tid >> 6;   // 0..3
    float* ob = out + ((size_t)(b * OUT_CH + g * FPG)) * (H * WID) + 4 * q;

    #pragma unroll 4
    for (int rr0 = 0; rr0 < TY; rr0 += 4) {
        const int rr = rr0 + r0;
        // window pairs p[dy][k] = (win[k], win[k+1]), win = padded cols 4q..4q+5
        uint64_t p[3][5];
        #pragma unroll
        for (int dy = 0; dy < 3; ++dy) {
            const float4* sp = (const float4*)(sm + (rr + dy) * SM_W + 4 * q);
            float4 a = sp[0], bb = sp[1];
            p[dy][0] = pk(a.x, a.y);
            p[dy][1] = pk(a.y, a.z);
            p[dy][2] = pk(a.z, a.w);
            p[dy][3] = pk(a.w, bb.x);
            p[dy][4] = pk(bb.x, bb.y);
        }
        const int y = tileY * TY + rr;
        #pragma unroll
        for (int o = 0; o < 8; ++o) {
            uint64_t acc01 = 0ull, acc23 = 0ull;   // (ax,ay), (az,aw)
            #pragma unroll
            for (int dy = 0; dy < 3; ++dy) {
                #pragma unroll
                for (int dx = 0; dx < 3; ++dx) {
                    const uint64_t ww = wsm2[o * 9 + dy * 3 + dx];
                    fma2(acc01, p[dy][dx], ww);
                    fma2(acc23, p[dy][dx + 2], ww);
                }
            }
            float ax, ay, az, aw;
            unpk(ax, ay, acc01);
            unpk(az, aw, acc23);
            *(float4*)(ob + (size_t)o * (H * WID) + (size_t)y * WID) =
                make_float4(ax, ay, az, aw);
        }
    }
}

extern "C" void kernel_launch(void* const* d_in, const int* in_sizes, int n_in,
                              void* d_out, int out_size) {
    const float* x   = (const float*)d_in[0];
    const float* rep = (const float*)d_in[1];
    const float* W   = (const float*)d_in[2];
    float* out = (float*)d_out;

    dim3 grid(H / TY, GROUPS, BATCH);
    fused_conv_kernel<<<grid, 256>>>(x, rep, W, out);
}